// round 1
// baseline (speedup 1.0000x reference)
#include <cuda_runtime.h>
#include <math.h>

#define SQ   4096
#define DIM  1024
#define NH   16
#define HD   64

// Scratch (allocation-free rule: __device__ globals)
__device__ float g_q[SQ * DIM];
__device__ float g_k[SQ * DIM];
__device__ float g_v[SQ * DIM];
__device__ float g_att[SQ * DIM];

// ---------------------------------------------------------------------------
// C[M,N] = A[M,K] @ B[N,K]^T + bias[N]
// BM=BN=64, BK=16, 256 threads, 4x4 register tile per thread.
// ---------------------------------------------------------------------------
__global__ __launch_bounds__(256) void gemm_nt_bias(
    const float* __restrict__ A, const float* __restrict__ B,
    const float* __restrict__ bias, float* __restrict__ C,
    int M, int N, int K)
{
    __shared__ float As[16][68];  // As[k][m]
    __shared__ float Bs[16][68];  // Bs[k][n]

    const int tid = threadIdx.x;
    const int tx = tid & 15;          // 0..15 (N dir)
    const int ty = tid >> 4;          // 0..15 (M dir)
    const int bm = blockIdx.y * 64;
    const int bn = blockIdx.x * 64;
    const int lr = tid >> 2;          // 0..63 row within tile for loads
    const int lc = tid & 3;           // 0..3  float4 slot

    float acc[4][4];
#pragma unroll
    for (int i = 0; i < 4; i++)
#pragma unroll
        for (int j = 0; j < 4; j++) acc[i][j] = 0.f;

    const float* Aptr = A + (size_t)(bm + lr) * K + lc * 4;
    const float* Bptr = B + (size_t)(bn + lr) * K + lc * 4;

    for (int kt = 0; kt < K; kt += 16) {
        float4 av = *(const float4*)(Aptr + kt);
        float4 bv = *(const float4*)(Bptr + kt);
        __syncthreads();
        As[lc * 4 + 0][lr] = av.x;
        As[lc * 4 + 1][lr] = av.y;
        As[lc * 4 + 2][lr] = av.z;
        As[lc * 4 + 3][lr] = av.w;
        Bs[lc * 4 + 0][lr] = bv.x;
        Bs[lc * 4 + 1][lr] = bv.y;
        Bs[lc * 4 + 2][lr] = bv.z;
        Bs[lc * 4 + 3][lr] = bv.w;
        __syncthreads();
#pragma unroll
        for (int k = 0; k < 16; k++) {
            float4 a = *(const float4*)&As[k][ty * 4];
            float4 b = *(const float4*)&Bs[k][tx * 4];
            float aa[4] = {a.x, a.y, a.z, a.w};
            float bb[4] = {b.x, b.y, b.z, b.w};
#pragma unroll
            for (int i = 0; i < 4; i++)
#pragma unroll
                for (int j = 0; j < 4; j++) acc[i][j] += aa[i] * bb[j];
        }
    }

#pragma unroll
    for (int i = 0; i < 4; i++) {
        int row = bm + ty * 4 + i;
        float4 o;
        o.x = acc[i][0] + bias[bn + tx * 4 + 0];
        o.y = acc[i][1] + bias[bn + tx * 4 + 1];
        o.z = acc[i][2] + bias[bn + tx * 4 + 2];
        o.w = acc[i][3] + bias[bn + tx * 4 + 3];
        *(float4*)&C[(size_t)row * N + bn + tx * 4] = o;
    }
}

// ---------------------------------------------------------------------------
// Flash attention with quantum-interference modulation.
// One block per (64-query tile, head). 256 threads.
// smem: Qs[64][68] (d-major), Ks[64][68] (d-major), Vs[64][64], Ss[64][68]
// Score phase:   thread (ty,tx) owns 4x4 of S
// Softmax/PV:    thread (r,g)  owns row r, cols g*16..g*16+15 of the output
// ---------------------------------------------------------------------------
#define QS_OFF 0
#define KS_OFF (64 * 68)
#define VS_OFF (2 * 64 * 68)
#define SS_OFF (2 * 64 * 68 + 64 * 64)
#define ATTN_SMEM_FLOATS (3 * 64 * 68 + 64 * 64)

__global__ __launch_bounds__(256) void attn_kernel(
    const float* __restrict__ Q, const float* __restrict__ K,
    const float* __restrict__ V, const float* __restrict__ phase,
    float* __restrict__ Out)
{
    extern __shared__ float smf[];
    float* Qs = smf + QS_OFF;
    float* Ks = smf + KS_OFF;
    float* Vs = smf + VS_OFF;
    float* Ss = smf + SS_OFF;

    const int h  = blockIdx.y;
    const int qb = blockIdx.x * 64;
    const int tid = threadIdx.x;
    const int tx = tid & 15, ty = tid >> 4;
    const int r  = tid >> 2, g  = tid & 3;
    const int hoff = h * HD;
    const float ph = phase[h];

    // Load Q tile transposed: Qs[d][i] = Q[qb+i][hoff+d]
    for (int f = tid; f < 64 * 16; f += 256) {
        int i = f >> 4, c4 = f & 15;
        float4 qv = *(const float4*)&Q[(size_t)(qb + i) * DIM + hoff + c4 * 4];
        Qs[(c4 * 4 + 0) * 68 + i] = qv.x;
        Qs[(c4 * 4 + 1) * 68 + i] = qv.y;
        Qs[(c4 * 4 + 2) * 68 + i] = qv.z;
        Qs[(c4 * 4 + 3) * 68 + i] = qv.w;
    }

    float m_run = -1e30f, l_run = 0.f;
    float acc[16];
#pragma unroll
    for (int c = 0; c < 16; c++) acc[c] = 0.f;
    __syncthreads();

    for (int kb = 0; kb < SQ; kb += 64) {
        // Load K tile (transposed) and V tile (direct)
        for (int f = tid; f < 64 * 16; f += 256) {
            int j = f >> 4, c4 = f & 15;
            float4 kv = *(const float4*)&K[(size_t)(kb + j) * DIM + hoff + c4 * 4];
            Ks[(c4 * 4 + 0) * 68 + j] = kv.x;
            Ks[(c4 * 4 + 1) * 68 + j] = kv.y;
            Ks[(c4 * 4 + 2) * 68 + j] = kv.z;
            Ks[(c4 * 4 + 3) * 68 + j] = kv.w;
            float4 vv = *(const float4*)&V[(size_t)(kb + j) * DIM + hoff + c4 * 4];
            *(float4*)&Vs[j * 64 + c4 * 4] = vv;
        }
        __syncthreads();

        // Scores S[i][j] = sum_d Qs[d][i] * Ks[d][j]
        float s[4][4];
#pragma unroll
        for (int i = 0; i < 4; i++)
#pragma unroll
            for (int j = 0; j < 4; j++) s[i][j] = 0.f;
#pragma unroll
        for (int d = 0; d < 64; d++) {
            float4 a = *(const float4*)&Qs[d * 68 + ty * 4];
            float4 b = *(const float4*)&Ks[d * 68 + tx * 4];
            float aa[4] = {a.x, a.y, a.z, a.w};
            float bb[4] = {b.x, b.y, b.z, b.w};
#pragma unroll
            for (int i = 0; i < 4; i++)
#pragma unroll
                for (int j = 0; j < 4; j++) s[i][j] += aa[i] * bb[j];
        }
        // Modulation: sc = s/8; sc * (1 + 0.1*cos(ph*sc))
#pragma unroll
        for (int i = 0; i < 4; i++) {
            float o[4];
#pragma unroll
            for (int j = 0; j < 4; j++) {
                float sc = s[i][j] * 0.125f;
                o[j] = sc * (1.f + 0.1f * __cosf(ph * sc));
            }
            float4 ov = {o[0], o[1], o[2], o[3]};
            *(float4*)&Ss[(ty * 4 + i) * 68 + tx * 4] = ov;
        }
        __syncthreads();

        // Online softmax: thread (r,g) handles cols g*16..g*16+15 of row r
        float pv[16];
        float tmax = -1e30f;
#pragma unroll
        for (int c = 0; c < 16; c++) {
            pv[c] = Ss[r * 68 + g * 16 + c];
            tmax = fmaxf(tmax, pv[c]);
        }
        tmax = fmaxf(tmax, __shfl_xor_sync(0xffffffffu, tmax, 1));
        tmax = fmaxf(tmax, __shfl_xor_sync(0xffffffffu, tmax, 2));
        float m_new = fmaxf(m_run, tmax);
        float corr  = __expf(m_run - m_new);
        float psum = 0.f;
#pragma unroll
        for (int c = 0; c < 16; c++) {
            float p = __expf(pv[c] - m_new);
            psum += p;
            Ss[r * 68 + g * 16 + c] = p;
        }
        psum += __shfl_xor_sync(0xffffffffu, psum, 1);
        psum += __shfl_xor_sync(0xffffffffu, psum, 2);
        l_run = l_run * corr + psum;
        m_run = m_new;
#pragma unroll
        for (int c = 0; c < 16; c++) acc[c] *= corr;
        __syncwarp();  // row-r P values written by the 4 same-warp threads

        // acc += P @ V   (thread (r,g): acc[c] over cols g*16+c)
#pragma unroll 8
        for (int j = 0; j < 64; j++) {
            float p = Ss[r * 68 + j];
            const float4* vrow = (const float4*)&Vs[j * 64 + g * 16];
            float4 v0 = vrow[0], v1 = vrow[1], v2 = vrow[2], v3 = vrow[3];
            acc[0]  += p * v0.x; acc[1]  += p * v0.y; acc[2]  += p * v0.z; acc[3]  += p * v0.w;
            acc[4]  += p * v1.x; acc[5]  += p * v1.y; acc[6]  += p * v1.z; acc[7]  += p * v1.w;
            acc[8]  += p * v2.x; acc[9]  += p * v2.y; acc[10] += p * v2.z; acc[11] += p * v2.w;
            acc[12] += p * v3.x; acc[13] += p * v3.y; acc[14] += p * v3.z; acc[15] += p * v3.w;
        }
        __syncthreads();  // protect Ks/Vs/Ss before next tile
    }

    float inv_l = 1.f / l_run;
#pragma unroll
    for (int c4 = 0; c4 < 4; c4++) {
        float4 o = {acc[c4 * 4 + 0] * inv_l, acc[c4 * 4 + 1] * inv_l,
                    acc[c4 * 4 + 2] * inv_l, acc[c4 * 4 + 3] * inv_l};
        *(float4*)&Out[(size_t)(qb + r) * DIM + hoff + g * 16 + c4 * 4] = o;
    }
}

// ---------------------------------------------------------------------------
extern "C" void kernel_launch(void* const* d_in, const int* in_sizes, int n_in,
                              void* d_out, int out_size)
{
    const float* x     = (const float*)d_in[0];
    const float* wq    = (const float*)d_in[1];
    const float* bq    = (const float*)d_in[2];
    const float* wk    = (const float*)d_in[3];
    const float* bk    = (const float*)d_in[4];
    const float* wv    = (const float*)d_in[5];
    const float* bv    = (const float*)d_in[6];
    const float* wo    = (const float*)d_in[7];
    const float* bo    = (const float*)d_in[8];
    const float* phase = (const float*)d_in[9];
    float* out = (float*)d_out;

    float *q, *k, *v, *att;
    cudaGetSymbolAddress((void**)&q,   g_q);
    cudaGetSymbolAddress((void**)&k,   g_k);
    cudaGetSymbolAddress((void**)&v,   g_v);
    cudaGetSymbolAddress((void**)&att, g_att);

    dim3 gblk(256);
    dim3 ggrid(DIM / 64, SQ / 64);  // (N/64, M/64)

    gemm_nt_bias<<<ggrid, gblk>>>(x, wq, bq, q, SQ, DIM, DIM);
    gemm_nt_bias<<<ggrid, gblk>>>(x, wk, bk, k, SQ, DIM, DIM);
    gemm_nt_bias<<<ggrid, gblk>>>(x, wv, bv, v, SQ, DIM, DIM);

    size_t attn_smem = ATTN_SMEM_FLOATS * sizeof(float);  // 68608 B
    cudaFuncSetAttribute(attn_kernel,
                         cudaFuncAttributeMaxDynamicSharedMemorySize,
                         (int)attn_smem);
    dim3 agrid(SQ / 64, NH);
    attn_kernel<<<agrid, 256, attn_smem>>>(q, k, v, phase, att);

    gemm_nt_bias<<<ggrid, gblk>>>(att, wo, bo, out, SQ, DIM, DIM);
}

// round 5
// speedup vs baseline: 2.9638x; 2.9638x over previous
#include <cuda_runtime.h>
#include <cuda_bf16.h>
#include <stdint.h>

#define SQ   4096
#define DIM  1024
#define NH   16
#define HD   64
#define QT   128   // queries per attention block
#define KT   64    // keys per tile

// Scratch (allocation-free rule: __device__ globals)
__device__ float        g_att[SQ * DIM];
__device__ __nv_bfloat16 g_qh[SQ * DIM], g_ql[SQ * DIM];
__device__ __nv_bfloat16 g_kh[SQ * DIM], g_kl[SQ * DIM];
__device__ __nv_bfloat16 g_vh[SQ * DIM], g_vl[SQ * DIM];

// ---------------------------------------------------------------------------
// Warp-MMA helpers (sm_80+ baseline PTX: works on sm_100 non-'a' targets)
// ---------------------------------------------------------------------------
__device__ __forceinline__ uint32_t smem_u32(const void* p) {
    uint32_t a;
    asm("{ .reg .u64 t; cvta.to.shared.u64 t, %1; cvt.u32.u64 %0, t; }"
        : "=r"(a) : "l"(p));
    return a;
}
// SW128-style XOR swizzle for 128B rows (bits[9:7] -> bits[6:4])
#define SWZ(off) ((off) ^ (((off) >> 3) & 0x70))

__device__ __forceinline__ void mma_bf16(float* d, const uint32_t* a,
                                         uint32_t b0, uint32_t b1) {
    asm volatile(
        "mma.sync.aligned.m16n8k16.row.col.f32.bf16.bf16.f32 "
        "{%0,%1,%2,%3}, {%4,%5,%6,%7}, {%8,%9}, {%0,%1,%2,%3};"
        : "+f"(d[0]), "+f"(d[1]), "+f"(d[2]), "+f"(d[3])
        : "r"(a[0]), "r"(a[1]), "r"(a[2]), "r"(a[3]), "r"(b0), "r"(b1));
}
__device__ __forceinline__ void ldm_x4(uint32_t* r, uint32_t addr) {
    asm volatile("ldmatrix.sync.aligned.m8n8.x4.shared.b16 {%0,%1,%2,%3}, [%4];"
        : "=r"(r[0]), "=r"(r[1]), "=r"(r[2]), "=r"(r[3]) : "r"(addr));
}
__device__ __forceinline__ void ldm_x4_t(uint32_t* r, uint32_t addr) {
    asm volatile("ldmatrix.sync.aligned.m8n8.x4.trans.shared.b16 {%0,%1,%2,%3}, [%4];"
        : "=r"(r[0]), "=r"(r[1]), "=r"(r[2]), "=r"(r[3]) : "r"(addr));
}

// ---------------------------------------------------------------------------
// Attention: mma.sync bf16 split (hi+lo), fixed-shift softmax (exp(s-16)).
// Block = 128 queries x 1 head; 256 threads = 8 warps; warp owns 16 q-rows.
// smem: Qh(16K) Ql(16K) Kh(8K) Kl(8K) Vh(8K) Vl(8K) = 64KB dynamic.
// ---------------------------------------------------------------------------
#define SM_QH 0
#define SM_QL 16384
#define SM_KH 32768
#define SM_KL 40960
#define SM_VH 49152
#define SM_VL 57344
#define ATT_SMEM 65536

__global__ void __launch_bounds__(256, 1) attn_mma(
    const __nv_bfloat16* __restrict__ Qh, const __nv_bfloat16* __restrict__ Ql,
    const __nv_bfloat16* __restrict__ Kh, const __nv_bfloat16* __restrict__ Kl,
    const __nv_bfloat16* __restrict__ Vh, const __nv_bfloat16* __restrict__ Vl,
    const float* __restrict__ phase, float* __restrict__ Out)
{
    extern __shared__ char sm[];
    const uint32_t smb = smem_u32(sm);
    const int tid  = threadIdx.x;
    const int lane = tid & 31;
    const int warp = tid >> 5;
    const int h  = blockIdx.y;
    const int qb = blockIdx.x * QT;
    const int m0 = warp * 16;
    const float ph = phase[h];

    // ---- stage Q hi/lo tiles (128 rows x 128B each) ----
    {
        const int buf = tid >> 7;          // 0: hi, 1: lo
        const int row = tid & 127;
        const __nv_bfloat16* src = (buf ? Ql : Qh) + (size_t)(qb + row) * DIM + h * HD;
        char* dst = sm + (buf ? SM_QL : SM_QH);
        const uint4* s4 = (const uint4*)src;
#pragma unroll
        for (int i = 0; i < 8; i++)
            *(uint4*)(dst + SWZ((uint32_t)(row * 128 + i * 16))) = s4[i];
    }
    __syncthreads();

    // ---- preload Q A-fragments (persist across all key tiles) ----
    uint32_t qfh[4][4], qfl[4][4];
    {
        const uint32_t qrow = (uint32_t)(m0 + (lane & 15));
        const uint32_t qcol = (uint32_t)((lane >> 4) * 16);
#pragma unroll
        for (int kk = 0; kk < 4; kk++) {
            uint32_t off = SWZ(qrow * 128 + kk * 32 + qcol);
            ldm_x4(qfh[kk], smb + SM_QH + off);
            ldm_x4(qfl[kk], smb + SM_QL + off);
        }
    }

    // ldmatrix per-lane geometry for K (B frags) and V (trans B frags)
    const uint32_t krow = (uint32_t)(((lane >> 4) << 3) + (lane & 7));
    const uint32_t kcol = (uint32_t)(((lane >> 3) & 1) * 16);
    const uint32_t vrow = (uint32_t)((((lane >> 3) & 1) << 3) + (lane & 7));
    const uint32_t vcol = (uint32_t)((lane >> 4) * 16);

    float o[8][4];
#pragma unroll
    for (int n = 0; n < 8; n++)
#pragma unroll
        for (int e = 0; e < 4; e++) o[n][e] = 0.f;
    float lsum0 = 0.f, lsum8 = 0.f;

    for (int t = 0; t < SQ / KT; t++) {
        const int kb = t * KT;
        if (t) __syncthreads();  // previous tile's compute done
        // ---- stage K/V hi/lo (4 bufs x 64 rows) ----
        {
            const int buf = tid >> 6;      // 0:Kh 1:Kl 2:Vh 3:Vl
            const int row = tid & 63;
            const __nv_bfloat16* srcs[4] = {Kh, Kl, Vh, Vl};
            const int offs[4] = {SM_KH, SM_KL, SM_VH, SM_VL};
            const uint4* s4 = (const uint4*)(srcs[buf] + (size_t)(kb + row) * DIM + h * HD);
            char* dst = sm + offs[buf];
#pragma unroll
            for (int i = 0; i < 8; i++)
                *(uint4*)(dst + SWZ((uint32_t)(row * 128 + i * 16))) = s4[i];
        }
        __syncthreads();

        // ---- S = Q K^T (split bf16: hh + hl + lh) ----
        float s[8][4];
#pragma unroll
        for (int n = 0; n < 8; n++)
#pragma unroll
            for (int e = 0; e < 4; e++) s[n][e] = 0.f;

#pragma unroll
        for (int kk = 0; kk < 4; kk++) {
#pragma unroll
            for (int np = 0; np < 4; np++) {
                uint32_t bh[4], bl[4];
                uint32_t off = SWZ((np * 16 + krow) * 128 + kk * 32 + kcol);
                ldm_x4(bh, smb + SM_KH + off);
                ldm_x4(bl, smb + SM_KL + off);
                mma_bf16(s[2*np],   qfh[kk], bh[0], bh[1]);
                mma_bf16(s[2*np],   qfh[kk], bl[0], bl[1]);
                mma_bf16(s[2*np],   qfl[kk], bh[0], bh[1]);
                mma_bf16(s[2*np+1], qfh[kk], bh[2], bh[3]);
                mma_bf16(s[2*np+1], qfh[kk], bl[2], bl[3]);
                mma_bf16(s[2*np+1], qfl[kk], bh[2], bh[3]);
            }
        }

        // ---- modulation + exp(. - 16); accumulate row sums ----
#pragma unroll
        for (int n = 0; n < 8; n++) {
#pragma unroll
            for (int e = 0; e < 4; e++) {
                float sc = s[n][e] * 0.125f;
                float m  = sc * (1.f + 0.1f * __cosf(ph * sc));
                s[n][e]  = __expf(m - 16.f);
            }
            lsum0 += s[n][0] + s[n][1];
            lsum8 += s[n][2] + s[n][3];
        }

        // ---- O += P V (P packed from S frags in registers) ----
#pragma unroll
        for (int kk = 0; kk < 4; kk++) {
            const int t0 = 2 * kk, t1 = 2 * kk + 1;
            uint32_t ah[4], al[4];
            const float* pv[4] = {&s[t0][0], &s[t0][2], &s[t1][0], &s[t1][2]};
#pragma unroll
            for (int q = 0; q < 4; q++) {
                float p0 = pv[q][0], p1 = pv[q][1];
                __nv_bfloat162 hp = __floats2bfloat162_rn(p0, p1);
                float r0 = p0 - __bfloat162float(hp.x);
                float r1 = p1 - __bfloat162float(hp.y);
                __nv_bfloat162 lp = __floats2bfloat162_rn(r0, r1);
                ah[q] = *(uint32_t*)&hp;
                al[q] = *(uint32_t*)&lp;
            }
#pragma unroll
            for (int dp = 0; dp < 4; dp++) {
                uint32_t bh[4], bl[4];
                uint32_t off = SWZ((kk * 16 + vrow) * 128 + dp * 32 + vcol);
                ldm_x4_t(bh, smb + SM_VH + off);
                ldm_x4_t(bl, smb + SM_VL + off);
                mma_bf16(o[2*dp],   ah, bh[0], bh[1]);
                mma_bf16(o[2*dp],   ah, bl[0], bl[1]);
                mma_bf16(o[2*dp],   al, bh[0], bh[1]);
                mma_bf16(o[2*dp+1], ah, bh[2], bh[3]);
                mma_bf16(o[2*dp+1], ah, bl[2], bl[3]);
                mma_bf16(o[2*dp+1], al, bh[2], bh[3]);
            }
        }
    }

    // ---- finalize: reduce l across the quad, scale, store ----
    lsum0 += __shfl_xor_sync(0xffffffffu, lsum0, 1);
    lsum0 += __shfl_xor_sync(0xffffffffu, lsum0, 2);
    lsum8 += __shfl_xor_sync(0xffffffffu, lsum8, 1);
    lsum8 += __shfl_xor_sync(0xffffffffu, lsum8, 2);
    const float inv0 = 1.f / lsum0;
    const float inv8 = 1.f / lsum8;

    const int row0 = qb + m0 + (lane >> 2);
    const int colb = h * HD + (lane & 3) * 2;
#pragma unroll
    for (int n = 0; n < 8; n++) {
        float2 w0 = {o[n][0] * inv0, o[n][1] * inv0};
        float2 w8 = {o[n][2] * inv8, o[n][3] * inv8};
        *(float2*)&Out[(size_t)row0 * DIM + colb + n * 8] = w0;
        *(float2*)&Out[(size_t)(row0 + 8) * DIM + colb + n * 8] = w8;
    }
}

// ---------------------------------------------------------------------------
// SIMT GEMM: C[M,N] = A @ B^T + bias (fp32 out) — used for O projection
// ---------------------------------------------------------------------------
__global__ __launch_bounds__(256) void gemm_nt_bias(
    const float* __restrict__ A, const float* __restrict__ B,
    const float* __restrict__ bias, float* __restrict__ C,
    int M, int N, int Kd)
{
    __shared__ float As[16][68];
    __shared__ float Bs[16][68];

    const int tid = threadIdx.x;
    const int tx = tid & 15, ty = tid >> 4;
    const int bm = blockIdx.y * 64, bn = blockIdx.x * 64;
    const int lr = tid >> 2, lc = tid & 3;

    float acc[4][4];
#pragma unroll
    for (int i = 0; i < 4; i++)
#pragma unroll
        for (int j = 0; j < 4; j++) acc[i][j] = 0.f;

    const float* Aptr = A + (size_t)(bm + lr) * Kd + lc * 4;
    const float* Bptr = B + (size_t)(bn + lr) * Kd + lc * 4;

    for (int kt = 0; kt < Kd; kt += 16) {
        float4 av = *(const float4*)(Aptr + kt);
        float4 bv = *(const float4*)(Bptr + kt);
        __syncthreads();
        As[lc*4+0][lr] = av.x; As[lc*4+1][lr] = av.y;
        As[lc*4+2][lr] = av.z; As[lc*4+3][lr] = av.w;
        Bs[lc*4+0][lr] = bv.x; Bs[lc*4+1][lr] = bv.y;
        Bs[lc*4+2][lr] = bv.z; Bs[lc*4+3][lr] = bv.w;
        __syncthreads();
#pragma unroll
        for (int k = 0; k < 16; k++) {
            float4 a = *(const float4*)&As[k][ty * 4];
            float4 b = *(const float4*)&Bs[k][tx * 4];
            float aa[4] = {a.x, a.y, a.z, a.w};
            float bb[4] = {b.x, b.y, b.z, b.w};
#pragma unroll
            for (int i = 0; i < 4; i++)
#pragma unroll
                for (int j = 0; j < 4; j++) acc[i][j] += aa[i] * bb[j];
        }
    }
#pragma unroll
    for (int i = 0; i < 4; i++) {
        int row = bm + ty * 4 + i;
        float4 out;
        out.x = acc[i][0] + bias[bn + tx*4 + 0];
        out.y = acc[i][1] + bias[bn + tx*4 + 1];
        out.z = acc[i][2] + bias[bn + tx*4 + 2];
        out.w = acc[i][3] + bias[bn + tx*4 + 3];
        *(float4*)&C[(size_t)row * N + bn + tx * 4] = out;
    }
}

// ---------------------------------------------------------------------------
// Same GEMM, epilogue writes bf16 hi + lo (split) — for Q/K/V projections
// ---------------------------------------------------------------------------
__global__ __launch_bounds__(256) void gemm_nt_bias_split(
    const float* __restrict__ A, const float* __restrict__ B,
    const float* __restrict__ bias,
    __nv_bfloat16* __restrict__ Chi, __nv_bfloat16* __restrict__ Clo,
    int M, int N, int Kd)
{
    __shared__ float As[16][68];
    __shared__ float Bs[16][68];

    const int tid = threadIdx.x;
    const int tx = tid & 15, ty = tid >> 4;
    const int bm = blockIdx.y * 64, bn = blockIdx.x * 64;
    const int lr = tid >> 2, lc = tid & 3;

    float acc[4][4];
#pragma unroll
    for (int i = 0; i < 4; i++)
#pragma unroll
        for (int j = 0; j < 4; j++) acc[i][j] = 0.f;

    const float* Aptr = A + (size_t)(bm + lr) * Kd + lc * 4;
    const float* Bptr = B + (size_t)(bn + lr) * Kd + lc * 4;

    for (int kt = 0; kt < Kd; kt += 16) {
        float4 av = *(const float4*)(Aptr + kt);
        float4 bv = *(const float4*)(Bptr + kt);
        __syncthreads();
        As[lc*4+0][lr] = av.x; As[lc*4+1][lr] = av.y;
        As[lc*4+2][lr] = av.z; As[lc*4+3][lr] = av.w;
        Bs[lc*4+0][lr] = bv.x; Bs[lc*4+1][lr] = bv.y;
        Bs[lc*4+2][lr] = bv.z; Bs[lc*4+3][lr] = bv.w;
        __syncthreads();
#pragma unroll
        for (int k = 0; k < 16; k++) {
            float4 a = *(const float4*)&As[k][ty * 4];
            float4 b = *(const float4*)&Bs[k][tx * 4];
            float aa[4] = {a.x, a.y, a.z, a.w};
            float bb[4] = {b.x, b.y, b.z, b.w};
#pragma unroll
            for (int i = 0; i < 4; i++)
#pragma unroll
                for (int j = 0; j < 4; j++) acc[i][j] += aa[i] * bb[j];
        }
    }
#pragma unroll
    for (int i = 0; i < 4; i++) {
        int row = bm + ty * 4 + i;
        size_t base = (size_t)row * N + bn + tx * 4;
        __nv_bfloat162 hi2[2], lo2[2];
#pragma unroll
        for (int p = 0; p < 2; p++) {
            float v0 = acc[i][2*p+0] + bias[bn + tx*4 + 2*p+0];
            float v1 = acc[i][2*p+1] + bias[bn + tx*4 + 2*p+1];
            __nv_bfloat162 hp = __floats2bfloat162_rn(v0, v1);
            float r0 = v0 - __bfloat162float(hp.x);
            float r1 = v1 - __bfloat162float(hp.y);
            hi2[p] = hp;
            lo2[p] = __floats2bfloat162_rn(r0, r1);
        }
        *(uint2*)&Chi[base] = *(uint2*)hi2;
        *(uint2*)&Clo[base] = *(uint2*)lo2;
    }
}

// ---------------------------------------------------------------------------
extern "C" void kernel_launch(void* const* d_in, const int* in_sizes, int n_in,
                              void* d_out, int out_size)
{
    const float* x     = (const float*)d_in[0];
    const float* wq    = (const float*)d_in[1];
    const float* bq    = (const float*)d_in[2];
    const float* wk    = (const float*)d_in[3];
    const float* bk    = (const float*)d_in[4];
    const float* wv    = (const float*)d_in[5];
    const float* bv    = (const float*)d_in[6];
    const float* wo    = (const float*)d_in[7];
    const float* bo    = (const float*)d_in[8];
    const float* phase = (const float*)d_in[9];
    float* out = (float*)d_out;

    float* att;
    __nv_bfloat16 *qh, *ql, *kh, *kl, *vh, *vl;
    cudaGetSymbolAddress((void**)&att, g_att);
    cudaGetSymbolAddress((void**)&qh, g_qh);
    cudaGetSymbolAddress((void**)&ql, g_ql);
    cudaGetSymbolAddress((void**)&kh, g_kh);
    cudaGetSymbolAddress((void**)&kl, g_kl);
    cudaGetSymbolAddress((void**)&vh, g_vh);
    cudaGetSymbolAddress((void**)&vl, g_vl);

    dim3 gblk(256);
    dim3 ggrid(DIM / 64, SQ / 64);

    gemm_nt_bias_split<<<ggrid, gblk>>>(x, wq, bq, qh, ql, SQ, DIM, DIM);
    gemm_nt_bias_split<<<ggrid, gblk>>>(x, wk, bk, kh, kl, SQ, DIM, DIM);
    gemm_nt_bias_split<<<ggrid, gblk>>>(x, wv, bv, vh, vl, SQ, DIM, DIM);

    cudaFuncSetAttribute(attn_mma, cudaFuncAttributeMaxDynamicSharedMemorySize,
                         ATT_SMEM);
    dim3 agrid(SQ / QT, NH);
    attn_mma<<<agrid, 256, ATT_SMEM>>>(qh, ql, kh, kl, vh, vl, phase, att);

    gemm_nt_bias<<<ggrid, gblk>>>(att, wo, bo, out, SQ, DIM, DIM);
}

// round 7
// speedup vs baseline: 4.3332x; 1.4620x over previous
#include <cuda_runtime.h>
#include <cuda_bf16.h>
#include <stdint.h>

#define SQ   4096
#define DIM  1024
#define NH   16
#define HD   64
#define QT   128
#define KT   64

// Scratch (allocation-free rule: __device__ globals)
__device__ __nv_bfloat16 g_xh[SQ * DIM],  g_xl[SQ * DIM];
__device__ __nv_bfloat16 g_wqh[DIM * DIM], g_wql[DIM * DIM];
__device__ __nv_bfloat16 g_wkh[DIM * DIM], g_wkl[DIM * DIM];
__device__ __nv_bfloat16 g_wvh[DIM * DIM], g_wvl[DIM * DIM];
__device__ __nv_bfloat16 g_woh[DIM * DIM], g_wol[DIM * DIM];
__device__ __nv_bfloat16 g_qh[SQ * DIM], g_ql[SQ * DIM];
__device__ __nv_bfloat16 g_kh[SQ * DIM], g_kl[SQ * DIM];
__device__ __nv_bfloat16 g_vh[SQ * DIM], g_vl[SQ * DIM];
__device__ __nv_bfloat16 g_oh[SQ * DIM], g_ol[SQ * DIM];

// ---------------------------------------------------------------------------
// Helpers
// ---------------------------------------------------------------------------
__device__ __forceinline__ uint32_t smem_u32(const void* p) {
    uint32_t a;
    asm("{ .reg .u64 t; cvta.to.shared.u64 t, %1; cvt.u32.u64 %0, t; }"
        : "=r"(a) : "l"(p));
    return a;
}
#define SWZ(off)  ((off) ^ (((off) >> 3) & 0x70))   // 128B rows
#define SW64(off) ((off) ^ (((off) >> 3) & 0x30))   // 64B rows

#define CP16(dst, src) \
    asm volatile("cp.async.cg.shared.global [%0], [%1], 16;" :: "r"(dst), "l"(src))
#define CP_COMMIT() asm volatile("cp.async.commit_group;" ::: "memory")
#define CP_WAIT1()  asm volatile("cp.async.wait_group 1;" ::: "memory")

__device__ __forceinline__ void mma_bf16(float* d, const uint32_t* a,
                                         uint32_t b0, uint32_t b1) {
    asm volatile(
        "mma.sync.aligned.m16n8k16.row.col.f32.bf16.bf16.f32 "
        "{%0,%1,%2,%3}, {%4,%5,%6,%7}, {%8,%9}, {%0,%1,%2,%3};"
        : "+f"(d[0]), "+f"(d[1]), "+f"(d[2]), "+f"(d[3])
        : "r"(a[0]), "r"(a[1]), "r"(a[2]), "r"(a[3]), "r"(b0), "r"(b1));
}
__device__ __forceinline__ void ldm_x4(uint32_t* r, uint32_t addr) {
    asm volatile("ldmatrix.sync.aligned.m8n8.x4.shared.b16 {%0,%1,%2,%3}, [%4];"
        : "=r"(r[0]), "=r"(r[1]), "=r"(r[2]), "=r"(r[3]) : "r"(addr));
}
__device__ __forceinline__ void ldm_x4_t(uint32_t* r, uint32_t addr) {
    asm volatile("ldmatrix.sync.aligned.m8n8.x4.trans.shared.b16 {%0,%1,%2,%3}, [%4];"
        : "=r"(r[0]), "=r"(r[1]), "=r"(r[2]), "=r"(r[3]) : "r"(addr));
}

// ---------------------------------------------------------------------------
// fp32 -> bf16 hi/lo split (elementwise)
// ---------------------------------------------------------------------------
__global__ void __launch_bounds__(256) split32(
    const float* __restrict__ in, __nv_bfloat16* __restrict__ hi,
    __nv_bfloat16* __restrict__ lo, int n)
{
    int i = (blockIdx.x * 256 + threadIdx.x) * 4;
    if (i >= n) return;
    float4 f = *(const float4*)(in + i);
    __nv_bfloat162 h0 = __floats2bfloat162_rn(f.x, f.y);
    __nv_bfloat162 h1 = __floats2bfloat162_rn(f.z, f.w);
    __nv_bfloat162 l0 = __floats2bfloat162_rn(f.x - __bfloat162float(h0.x),
                                              f.y - __bfloat162float(h0.y));
    __nv_bfloat162 l1 = __floats2bfloat162_rn(f.z - __bfloat162float(h1.x),
                                              f.w - __bfloat162float(h1.y));
    uint2 hv = {*(uint32_t*)&h0, *(uint32_t*)&h1};
    uint2 lv = {*(uint32_t*)&l0, *(uint32_t*)&l1};
    *(uint2*)(hi + i) = hv;
    *(uint2*)(lo + i) = lv;
}

// ---------------------------------------------------------------------------
// Split-bf16 tensor GEMM: C[M,N] = A @ B^T + bias, M=SQ, N=K=DIM.
// BM=128, BN=128, k-step 32, cp.async double buffer (2 x 32KB).
// 256 threads = 8 warps (2m x 4n), warp tile 64x32.
// SPLIT_OUT: 0 -> fp32 C; 1 -> bf16 hi/lo pair.
// ---------------------------------------------------------------------------
#define GS_STAGE 32768

template<int SPLIT_OUT>
__global__ void __launch_bounds__(256, 1) gemm_mma(
    const __nv_bfloat16* __restrict__ Agh, const __nv_bfloat16* __restrict__ Agl,
    const __nv_bfloat16* __restrict__ Bgh, const __nv_bfloat16* __restrict__ Bgl,
    const float* __restrict__ bias, float* __restrict__ C,
    __nv_bfloat16* __restrict__ Chi, __nv_bfloat16* __restrict__ Clo)
{
    extern __shared__ char sm[];
    const uint32_t smb = smem_u32(sm);
    const int tid = threadIdx.x, lane = tid & 31, warp = tid >> 5;
    const int bm = blockIdx.y * 128, bn = blockIdx.x * 128;
    const int wm = (warp >> 2) * 64, wn = (warp & 3) * 32;

    // loader role: buf 0:Ah 1:Al 2:Bh 3:Bl; 64 threads per buf, 2 rows each
    const int buf = tid >> 6, lrow = tid & 63;
    const __nv_bfloat16* gp[4] = {Agh, Agl, Bgh, Bgl};
    const int rbase = (buf < 2 ? bm : bn) + lrow;
    const __nv_bfloat16* src0 = gp[buf] + (size_t)rbase * DIM;
    const __nv_bfloat16* src1 = gp[buf] + (size_t)(rbase + 64) * DIM;

    float acc[4][4][4];
#pragma unroll
    for (int a = 0; a < 4; a++)
#pragma unroll
        for (int b = 0; b < 4; b++)
#pragma unroll
            for (int c = 0; c < 4; c++) acc[a][b][c] = 0.f;

    // prologue: stage 0
    {
        uint32_t db = smb + buf * 8192;
#pragma unroll
        for (int i = 0; i < 4; i++) {
            CP16(db + SW64((uint32_t)(lrow * 64 + i * 16)),        src0 + i * 8);
            CP16(db + SW64((uint32_t)((lrow + 64) * 64 + i * 16)), src1 + i * 8);
        }
    }
    CP_COMMIT();

    for (int kt = 0; kt < 32; kt++) {
        if (kt + 1 < 32) {
            uint32_t db = smb + ((kt + 1) & 1) * GS_STAGE + buf * 8192;
            const __nv_bfloat16* s0 = src0 + (kt + 1) * 32;
            const __nv_bfloat16* s1 = src1 + (kt + 1) * 32;
#pragma unroll
            for (int i = 0; i < 4; i++) {
                CP16(db + SW64((uint32_t)(lrow * 64 + i * 16)),        s0 + i * 8);
                CP16(db + SW64((uint32_t)((lrow + 64) * 64 + i * 16)), s1 + i * 8);
            }
        }
        CP_COMMIT();
        CP_WAIT1();
        __syncthreads();

        const uint32_t sb = smb + (kt & 1) * GS_STAGE;
#pragma unroll
        for (int kk = 0; kk < 2; kk++) {
            uint32_t ah[4][4], al[4][4];
#pragma unroll
            for (int mf = 0; mf < 4; mf++) {
                uint32_t off = SW64((uint32_t)((wm + mf * 16 + (lane & 15)) * 64
                                    + kk * 32 + (lane >> 4) * 16));
                ldm_x4(ah[mf], sb + off);
                ldm_x4(al[mf], sb + 8192 + off);
            }
#pragma unroll
            for (int nf = 0; nf < 2; nf++) {
                uint32_t bh[4], bl[4];
                uint32_t off = SW64((uint32_t)((wn + nf * 16 + ((lane >> 4) << 3)
                                    + (lane & 7)) * 64 + kk * 32
                                    + ((lane >> 3) & 1) * 16));
                ldm_x4(bh, sb + 16384 + off);
                ldm_x4(bl, sb + 24576 + off);
#pragma unroll
                for (int mf = 0; mf < 4; mf++) {
                    mma_bf16(acc[mf][2*nf],   ah[mf], bh[0], bh[1]);
                    mma_bf16(acc[mf][2*nf],   ah[mf], bl[0], bl[1]);
                    mma_bf16(acc[mf][2*nf],   al[mf], bh[0], bh[1]);
                    mma_bf16(acc[mf][2*nf+1], ah[mf], bh[2], bh[3]);
                    mma_bf16(acc[mf][2*nf+1], ah[mf], bl[2], bl[3]);
                    mma_bf16(acc[mf][2*nf+1], al[mf], bh[2], bh[3]);
                }
            }
        }
        __syncthreads();
    }

    // epilogue
#pragma unroll
    for (int mf = 0; mf < 4; mf++) {
        int r0 = bm + wm + mf * 16 + (lane >> 2);
#pragma unroll
        for (int nf8 = 0; nf8 < 4; nf8++) {
            int c = bn + wn + nf8 * 8 + (lane & 3) * 2;
            float b0 = bias[c], b1 = bias[c + 1];
            float v0 = acc[mf][nf8][0] + b0, v1 = acc[mf][nf8][1] + b1;
            float v2 = acc[mf][nf8][2] + b0, v3 = acc[mf][nf8][3] + b1;
            if (SPLIT_OUT) {
                __nv_bfloat162 h0 = __floats2bfloat162_rn(v0, v1);
                __nv_bfloat162 l0 = __floats2bfloat162_rn(v0 - __bfloat162float(h0.x),
                                                          v1 - __bfloat162float(h0.y));
                __nv_bfloat162 h1 = __floats2bfloat162_rn(v2, v3);
                __nv_bfloat162 l1 = __floats2bfloat162_rn(v2 - __bfloat162float(h1.x),
                                                          v3 - __bfloat162float(h1.y));
                *(uint32_t*)&Chi[(size_t)r0 * DIM + c]       = *(uint32_t*)&h0;
                *(uint32_t*)&Clo[(size_t)r0 * DIM + c]       = *(uint32_t*)&l0;
                *(uint32_t*)&Chi[(size_t)(r0 + 8) * DIM + c] = *(uint32_t*)&h1;
                *(uint32_t*)&Clo[(size_t)(r0 + 8) * DIM + c] = *(uint32_t*)&l1;
            } else {
                float2 w0 = {v0, v1}, w1 = {v2, v3};
                *(float2*)&C[(size_t)r0 * DIM + c]       = w0;
                *(float2*)&C[(size_t)(r0 + 8) * DIM + c] = w1;
            }
        }
    }
}

// ---------------------------------------------------------------------------
// Attention: mma.sync split bf16, fixed-shift softmax, cp.async double-buffer.
// smem: Q 32KB (Qh/Ql) + 2 KV stages x 32KB (Kh,Kl,Vh,Vl @ 8KB each) = 96KB.
// ---------------------------------------------------------------------------
#define SM_Q0   0
#define SM_KV0  32768
#define ATT_SMEM 98304

__global__ void __launch_bounds__(256, 1) attn_mma(
    const __nv_bfloat16* __restrict__ Qh, const __nv_bfloat16* __restrict__ Ql,
    const __nv_bfloat16* __restrict__ Kh, const __nv_bfloat16* __restrict__ Kl,
    const __nv_bfloat16* __restrict__ Vh, const __nv_bfloat16* __restrict__ Vl,
    const float* __restrict__ phase,
    __nv_bfloat16* __restrict__ Oh, __nv_bfloat16* __restrict__ Ol)
{
    extern __shared__ char sm[];
    const uint32_t smb = smem_u32(sm);
    const int tid  = threadIdx.x;
    const int lane = tid & 31;
    const int warp = tid >> 5;
    const int h  = blockIdx.y;
    const int qb = blockIdx.x * QT;
    const int m0 = warp * 16;
    const float ph = phase[h];

    // KV loader role: buf 0:Kh 1:Kl 2:Vh 3:Vl; one 128B row per thread
    const int buf = tid >> 6, lrow = tid & 63;
    const __nv_bfloat16* gkv[4] = {Kh, Kl, Vh, Vl};
    const __nv_bfloat16* kvsrc = gkv[buf] + (size_t)lrow * DIM + h * HD;

    // prologue: prefetch KV tile 0
    {
        uint32_t db = smb + SM_KV0 + buf * 8192;
#pragma unroll
        for (int i = 0; i < 8; i++)
            CP16(db + SWZ((uint32_t)(lrow * 128 + i * 16)), kvsrc + i * 8);
    }
    CP_COMMIT();

    // stage Q hi/lo tiles (128 rows x 128B each)
    {
        const int qbuf = tid >> 7;          // 0: hi, 1: lo
        const int row = tid & 127;
        const __nv_bfloat16* src = (qbuf ? Ql : Qh) + (size_t)(qb + row) * DIM + h * HD;
        char* dst = sm + SM_Q0 + qbuf * 16384;
        const uint4* s4 = (const uint4*)src;
#pragma unroll
        for (int i = 0; i < 8; i++)
            *(uint4*)(dst + SWZ((uint32_t)(row * 128 + i * 16))) = s4[i];
    }
    __syncthreads();

    // preload Q A-fragments
    uint32_t qfh[4][4], qfl[4][4];
    {
        const uint32_t qrow = (uint32_t)(m0 + (lane & 15));
        const uint32_t qcol = (uint32_t)((lane >> 4) * 16);
#pragma unroll
        for (int kk = 0; kk < 4; kk++) {
            uint32_t off = SWZ(qrow * 128 + kk * 32 + qcol);
            ldm_x4(qfh[kk], smb + SM_Q0 + off);
            ldm_x4(qfl[kk], smb + SM_Q0 + 16384 + off);
        }
    }

    const uint32_t krow = (uint32_t)(((lane >> 4) << 3) + (lane & 7));
    const uint32_t kcol = (uint32_t)(((lane >> 3) & 1) * 16);
    const uint32_t vrow = (uint32_t)((((lane >> 3) & 1) << 3) + (lane & 7));
    const uint32_t vcol = (uint32_t)((lane >> 4) * 16);

    float o[8][4];
#pragma unroll
    for (int n = 0; n < 8; n++)
#pragma unroll
        for (int e = 0; e < 4; e++) o[n][e] = 0.f;
    float lsum0 = 0.f, lsum8 = 0.f;

    for (int t = 0; t < SQ / KT; t++) {
        // prefetch next KV tile into other stage
        if (t + 1 < SQ / KT) {
            uint32_t db = smb + SM_KV0 + ((t + 1) & 1) * 32768 + buf * 8192;
            const __nv_bfloat16* s = kvsrc + (size_t)(t + 1) * KT * DIM;
#pragma unroll
            for (int i = 0; i < 8; i++)
                CP16(db + SWZ((uint32_t)(lrow * 128 + i * 16)), s + i * 8);
        }
        CP_COMMIT();
        CP_WAIT1();
        __syncthreads();

        const uint32_t kvb = smb + SM_KV0 + (t & 1) * 32768;

        // ---- S = Q K^T (hh + hl + lh) ----
        float s[8][4];
#pragma unroll
        for (int n = 0; n < 8; n++)
#pragma unroll
            for (int e = 0; e < 4; e++) s[n][e] = 0.f;

#pragma unroll
        for (int kk = 0; kk < 4; kk++) {
#pragma unroll
            for (int np = 0; np < 4; np++) {
                uint32_t bh[4], bl[4];
                uint32_t off = SWZ((np * 16 + krow) * 128 + kk * 32 + kcol);
                ldm_x4(bh, kvb + off);
                ldm_x4(bl, kvb + 8192 + off);
                mma_bf16(s[2*np],   qfh[kk], bh[0], bh[1]);
                mma_bf16(s[2*np],   qfh[kk], bl[0], bl[1]);
                mma_bf16(s[2*np],   qfl[kk], bh[0], bh[1]);
                mma_bf16(s[2*np+1], qfh[kk], bh[2], bh[3]);
                mma_bf16(s[2*np+1], qfh[kk], bl[2], bl[3]);
                mma_bf16(s[2*np+1], qfl[kk], bh[2], bh[3]);
            }
        }

        // ---- modulation + exp(. - 16) ----
#pragma unroll
        for (int n = 0; n < 8; n++) {
#pragma unroll
            for (int e = 0; e < 4; e++) {
                float sc = s[n][e] * 0.125f;
                float m  = sc * (1.f + 0.1f * __cosf(ph * sc));
                s[n][e]  = __expf(m - 16.f);
            }
            lsum0 += s[n][0] + s[n][1];
            lsum8 += s[n][2] + s[n][3];
        }

        // ---- O += P V ----
#pragma unroll
        for (int kk = 0; kk < 4; kk++) {
            const int t0 = 2 * kk, t1 = 2 * kk + 1;
            uint32_t ah[4], al[4];
            const float* pv[4] = {&s[t0][0], &s[t0][2], &s[t1][0], &s[t1][2]};
#pragma unroll
            for (int q = 0; q < 4; q++) {
                float p0 = pv[q][0], p1 = pv[q][1];
                __nv_bfloat162 hp = __floats2bfloat162_rn(p0, p1);
                float r0 = p0 - __bfloat162float(hp.x);
                float r1 = p1 - __bfloat162float(hp.y);
                __nv_bfloat162 lp = __floats2bfloat162_rn(r0, r1);
                ah[q] = *(uint32_t*)&hp;
                al[q] = *(uint32_t*)&lp;
            }
#pragma unroll
            for (int dp = 0; dp < 4; dp++) {
                uint32_t bh[4], bl[4];
                uint32_t off = SWZ((kk * 16 + vrow) * 128 + dp * 32 + vcol);
                ldm_x4_t(bh, kvb + 16384 + off);
                ldm_x4_t(bl, kvb + 24576 + off);
                mma_bf16(o[2*dp],   ah, bh[0], bh[1]);
                mma_bf16(o[2*dp],   ah, bl[0], bl[1]);
                mma_bf16(o[2*dp],   al, bh[0], bh[1]);
                mma_bf16(o[2*dp+1], ah, bh[2], bh[3]);
                mma_bf16(o[2*dp+1], ah, bl[2], bl[3]);
                mma_bf16(o[2*dp+1], al, bh[2], bh[3]);
            }
        }
        __syncthreads();
    }

    // ---- finalize: l-reduce, scale, write split bf16 ----
    lsum0 += __shfl_xor_sync(0xffffffffu, lsum0, 1);
    lsum0 += __shfl_xor_sync(0xffffffffu, lsum0, 2);
    lsum8 += __shfl_xor_sync(0xffffffffu, lsum8, 1);
    lsum8 += __shfl_xor_sync(0xffffffffu, lsum8, 2);
    const float inv0 = 1.f / lsum0;
    const float inv8 = 1.f / lsum8;

    const int row0 = qb + m0 + (lane >> 2);
    const int colb = h * HD + (lane & 3) * 2;
#pragma unroll
    for (int n = 0; n < 8; n++) {
        float a0 = o[n][0] * inv0, a1 = o[n][1] * inv0;
        float b0 = o[n][2] * inv8, b1 = o[n][3] * inv8;
        __nv_bfloat162 h0 = __floats2bfloat162_rn(a0, a1);
        __nv_bfloat162 l0 = __floats2bfloat162_rn(a0 - __bfloat162float(h0.x),
                                                  a1 - __bfloat162float(h0.y));
        __nv_bfloat162 h1 = __floats2bfloat162_rn(b0, b1);
        __nv_bfloat162 l1 = __floats2bfloat162_rn(b0 - __bfloat162float(h1.x),
                                                  b1 - __bfloat162float(h1.y));
        size_t i0 = (size_t)row0 * DIM + colb + n * 8;
        size_t i1 = (size_t)(row0 + 8) * DIM + colb + n * 8;
        *(uint32_t*)&Oh[i0] = *(uint32_t*)&h0;
        *(uint32_t*)&Ol[i0] = *(uint32_t*)&l0;
        *(uint32_t*)&Oh[i1] = *(uint32_t*)&h1;
        *(uint32_t*)&Ol[i1] = *(uint32_t*)&l1;
    }
}

// ---------------------------------------------------------------------------
extern "C" void kernel_launch(void* const* d_in, const int* in_sizes, int n_in,
                              void* d_out, int out_size)
{
    const float* x     = (const float*)d_in[0];
    const float* wq    = (const float*)d_in[1];
    const float* bq    = (const float*)d_in[2];
    const float* wk    = (const float*)d_in[3];
    const float* bk    = (const float*)d_in[4];
    const float* wv    = (const float*)d_in[5];
    const float* bv    = (const float*)d_in[6];
    const float* wo    = (const float*)d_in[7];
    const float* bo    = (const float*)d_in[8];
    const float* phase = (const float*)d_in[9];
    float* out = (float*)d_out;

    __nv_bfloat16 *xh, *xl, *wqh, *wql, *wkh, *wkl, *wvh, *wvl, *woh, *wol;
    __nv_bfloat16 *qh, *ql, *kh, *kl, *vh, *vl, *oh, *ol;
    cudaGetSymbolAddress((void**)&xh,  g_xh);  cudaGetSymbolAddress((void**)&xl,  g_xl);
    cudaGetSymbolAddress((void**)&wqh, g_wqh); cudaGetSymbolAddress((void**)&wql, g_wql);
    cudaGetSymbolAddress((void**)&wkh, g_wkh); cudaGetSymbolAddress((void**)&wkl, g_wkl);
    cudaGetSymbolAddress((void**)&wvh, g_wvh); cudaGetSymbolAddress((void**)&wvl, g_wvl);
    cudaGetSymbolAddress((void**)&woh, g_woh); cudaGetSymbolAddress((void**)&wol, g_wol);
    cudaGetSymbolAddress((void**)&qh, g_qh); cudaGetSymbolAddress((void**)&ql, g_ql);
    cudaGetSymbolAddress((void**)&kh, g_kh); cudaGetSymbolAddress((void**)&kl, g_kl);
    cudaGetSymbolAddress((void**)&vh, g_vh); cudaGetSymbolAddress((void**)&vl, g_vl);
    cudaGetSymbolAddress((void**)&oh, g_oh); cudaGetSymbolAddress((void**)&ol, g_ol);

    // splits
    split32<<<SQ * DIM / 1024, 256>>>(x, xh, xl, SQ * DIM);
    split32<<<DIM * DIM / 1024, 256>>>(wq, wqh, wql, DIM * DIM);
    split32<<<DIM * DIM / 1024, 256>>>(wk, wkh, wkl, DIM * DIM);
    split32<<<DIM * DIM / 1024, 256>>>(wv, wvh, wvl, DIM * DIM);
    split32<<<DIM * DIM / 1024, 256>>>(wo, woh, wol, DIM * DIM);

    cudaFuncSetAttribute(gemm_mma<1>, cudaFuncAttributeMaxDynamicSharedMemorySize, 65536);
    cudaFuncSetAttribute(gemm_mma<0>, cudaFuncAttributeMaxDynamicSharedMemorySize, 65536);
    cudaFuncSetAttribute(attn_mma,    cudaFuncAttributeMaxDynamicSharedMemorySize, ATT_SMEM);

    dim3 ggrid(DIM / 128, SQ / 128);
    gemm_mma<1><<<ggrid, 256, 65536>>>(xh, xl, wqh, wql, bq, nullptr, qh, ql);
    gemm_mma<1><<<ggrid, 256, 65536>>>(xh, xl, wkh, wkl, bk, nullptr, kh, kl);
    gemm_mma<1><<<ggrid, 256, 65536>>>(xh, xl, wvh, wvl, bv, nullptr, vh, vl);

    dim3 agrid(SQ / QT, NH);
    attn_mma<<<agrid, 256, ATT_SMEM>>>(qh, ql, kh, kl, vh, vl, phase, oh, ol);

    gemm_mma<0><<<ggrid, 256, 65536>>>(oh, ol, woh, wol, bo, out, nullptr, nullptr);
}